// round 2
// baseline (speedup 1.0000x reference)
#include <cuda_runtime.h>
#include <cstdint>

#define NB  8
#define NS  1024
#define NXD 1024
#define NH  16
#define DH  64

// Scratch (device globals — no runtime allocation allowed)
__device__ float g_q[NB*NH*NS*DH];   // [B,H,S,HD]
__device__ float g_k[NB*NH*NS*DH];
__device__ float g_v[NB*NH*NS*DH];
__device__ float g_a[NB*NS*NXD];     // attention output, [B,S,NX]

// ---------------------------------------------------------------------------
// Packed f32x2 helpers (sm_103a dual fp32 pipe, PTX-only)
// ---------------------------------------------------------------------------
#define FMA2(d, a, b) asm("fma.rn.f32x2 %0, %1, %2, %0;" : "+l"(d) : "l"(a), "l"(b))
#define MUL2(d, s)    asm("mul.rn.f32x2 %0, %0, %1;" : "+l"(d) : "l"(s))
#define PACK2(d, x)   asm("mov.b64 %0, {%1, %1};" : "=l"(d) : "r"(__float_as_uint(x)))
#define UNPK2(lo, hi, d) asm("mov.b64 {%0, %1}, %2;" : "=r"(lo), "=r"(hi) : "l"(d))

// ---------------------------------------------------------------------------
// tf32 mma helpers
// ---------------------------------------------------------------------------
__device__ __forceinline__ void tf32split(float x, uint32_t& hi, uint32_t& lo) {
    uint32_t h;
    asm("cvt.rna.tf32.f32 %0, %1;" : "=r"(h) : "f"(x));
    float r = x - __uint_as_float(h);
    uint32_t l;
    asm("cvt.rna.tf32.f32 %0, %1;" : "=r"(l) : "f"(r));
    hi = h; lo = l;
}

__device__ __forceinline__ void mma8(const uint32_t a[4], const uint32_t b[2],
                                     float c[4]) {
    asm volatile(
        "mma.sync.aligned.m16n8k8.row.col.f32.tf32.tf32.f32 "
        "{%0,%1,%2,%3}, {%4,%5,%6,%7}, {%8,%9}, {%0,%1,%2,%3};\n"
        : "+f"(c[0]), "+f"(c[1]), "+f"(c[2]), "+f"(c[3])
        : "r"(a[0]), "r"(a[1]), "r"(a[2]), "r"(a[3]), "r"(b[0]), "r"(b[1]));
}

// ---------------------------------------------------------------------------
// Shared GEMM mainloop: block tile 128(M) x 64(N), BK=16, 256 threads.
// 8 warps in a 4x2 grid; warp tile 32x32 = 2 m16 frags x 4 n8 frags.
// 3xTF32: acc += Ahi*Bhi + Ahi*Blo + Alo*Bhi  (fp32-class accuracy).
// A row-major [.,1024], B row-major [1024, ldb].
// ---------------------------------------------------------------------------
__device__ __forceinline__ void run_gemm(
    const float* __restrict__ A, const float* __restrict__ B, int ldb,
    int m0, int n0, float (&acc)[2][4][4],
    float* As /*128*20*/, float* Bs /*16*72*/)
{
    const int tid  = threadIdx.x;
    const int lane = tid & 31;
    const int wid  = tid >> 5;
    const int warpM = wid >> 1;     // 0..3
    const int warpN = wid & 1;      // 0..1
    const int g  = lane >> 2;       // 0..7
    const int tg = lane & 3;        // 0..3

    #pragma unroll
    for (int mt = 0; mt < 2; mt++)
        #pragma unroll
        for (int nt = 0; nt < 4; nt++)
            #pragma unroll
            for (int r = 0; r < 4; r++) acc[mt][nt][r] = 0.f;

    // global-load indexing
    const int arow  = tid >> 2;           // 0..63 (and +64)
    const int acol  = (tid & 3) << 2;     // 0,4,8,12
    const int brow  = tid >> 4;           // 0..15
    const int bcol  = (tid & 15) << 2;    // 0..60

    const float* Ap0 = A + (size_t)(m0 + arow) * 1024 + acol;
    const float* Ap1 = A + (size_t)(m0 + arow + 64) * 1024 + acol;
    const float* Bp  = B + (size_t)brow * ldb + n0 + bcol;

    float4 pa0 = *(const float4*)Ap0;
    float4 pa1 = *(const float4*)Ap1;
    float4 pb  = *(const float4*)Bp;

    for (int k0 = 0; k0 < 1024; k0 += 16) {
        __syncthreads();
        *(float4*)&As[arow * 20 + acol]        = pa0;
        *(float4*)&As[(arow + 64) * 20 + acol] = pa1;
        *(float4*)&Bs[brow * 72 + bcol]        = pb;
        __syncthreads();
        if (k0 + 16 < 1024) {
            pa0 = *(const float4*)(Ap0 + k0 + 16);
            pa1 = *(const float4*)(Ap1 + k0 + 16);
            pb  = *(const float4*)(Bp + (size_t)(k0 + 16) * ldb);
        }

        #pragma unroll
        for (int kk = 0; kk < 16; kk += 8) {
            uint32_t ah[2][4], al[2][4];
            #pragma unroll
            for (int mt = 0; mt < 2; mt++) {
                const int mr = warpM * 32 + mt * 16 + g;
                float x0 = As[mr * 20 + kk + tg];
                float x1 = As[(mr + 8) * 20 + kk + tg];
                float x2 = As[mr * 20 + kk + tg + 4];
                float x3 = As[(mr + 8) * 20 + kk + tg + 4];
                tf32split(x0, ah[mt][0], al[mt][0]);
                tf32split(x1, ah[mt][1], al[mt][1]);
                tf32split(x2, ah[mt][2], al[mt][2]);
                tf32split(x3, ah[mt][3], al[mt][3]);
            }
            uint32_t bh[4][2], bl[4][2];
            #pragma unroll
            for (int nt = 0; nt < 4; nt++) {
                const int nc = warpN * 32 + nt * 8 + g;
                float y0 = Bs[(kk + tg) * 72 + nc];
                float y1 = Bs[(kk + tg + 4) * 72 + nc];
                tf32split(y0, bh[nt][0], bl[nt][0]);
                tf32split(y1, bh[nt][1], bl[nt][1]);
            }
            #pragma unroll
            for (int mt = 0; mt < 2; mt++)
                #pragma unroll
                for (int nt = 0; nt < 4; nt++) {
                    mma8(ah[mt], bh[nt], acc[mt][nt]);
                    mma8(ah[mt], bl[nt], acc[mt][nt]);
                    mma8(al[mt], bh[nt], acc[mt][nt]);
                }
        }
    }
}

// ---------------------------------------------------------------------------
// QKV projection: C[8192,3072] = A @ W + b, scattered into q/k/v [B,H,S,HD].
// Region (q/k/v) is constant per block since BN=64 divides 1024.
// ---------------------------------------------------------------------------
__global__ __launch_bounds__(256) void qkv_gemm(
    const float* __restrict__ x, const float* __restrict__ query,
    const float* __restrict__ W, const float* __restrict__ bias)
{
    __shared__ float As[128 * 20];
    __shared__ float Bs[16 * 72];

    const int n0 = blockIdx.x * 64;
    const int m0 = blockIdx.y * 128;
    const int region = n0 >> 10;                 // 0=q, 1=k, 2=v
    const float* A = (region == 0) ? query : x;
    float* dst = (region == 0) ? g_q : ((region == 1) ? g_k : g_v);

    float acc[2][4][4];
    run_gemm(A, W, 3072, m0, n0, acc, As, Bs);

    const int lane = threadIdx.x & 31;
    const int wid  = threadIdx.x >> 5;
    const int warpM = wid >> 1, warpN = wid & 1;
    const int g = lane >> 2, tg = lane & 3;

    #pragma unroll
    for (int mt = 0; mt < 2; mt++) {
        #pragma unroll
        for (int nt = 0; nt < 4; nt++) {
            const int row0 = m0 + warpM * 32 + mt * 16 + g;
            const int col0 = n0 + warpN * 32 + nt * 8 + 2 * tg;
            #pragma unroll
            for (int r = 0; r < 4; r++) {
                const int row = row0 + ((r >= 2) ? 8 : 0);
                const int col = col0 + (r & 1);
                const int bb = row >> 10, ss = row & 1023;
                const int nn = col & 1023;
                const int hh = nn >> 6, dd = nn & 63;
                dst[((size_t)((bb * NH + hh) * NS + ss)) * DH + dd] =
                    acc[mt][nt][r] + bias[col];
            }
        }
    }
}

// ---------------------------------------------------------------------------
// Output projection: out[8192,1024] = g_a @ Wp + bp
// ---------------------------------------------------------------------------
__global__ __launch_bounds__(256) void proj_gemm(
    const float* __restrict__ W, const float* __restrict__ bias,
    float* __restrict__ out)
{
    __shared__ float As[128 * 20];
    __shared__ float Bs[16 * 72];

    const int n0 = blockIdx.x * 64;
    const int m0 = blockIdx.y * 128;

    float acc[2][4][4];
    run_gemm(g_a, W, 1024, m0, n0, acc, As, Bs);

    const int lane = threadIdx.x & 31;
    const int wid  = threadIdx.x >> 5;
    const int warpM = wid >> 1, warpN = wid & 1;
    const int g = lane >> 2, tg = lane & 3;

    #pragma unroll
    for (int mt = 0; mt < 2; mt++) {
        #pragma unroll
        for (int nt = 0; nt < 4; nt++) {
            const int row0 = m0 + warpM * 32 + mt * 16 + g;
            const int col0 = n0 + warpN * 32 + nt * 8 + 2 * tg;
            #pragma unroll
            for (int r = 0; r < 4; r++) {
                const int row = row0 + ((r >= 2) ? 8 : 0);
                const int col = col0 + (r & 1);
                out[(size_t)row * NXD + col] = acc[mt][nt][r] + bias[col];
            }
        }
    }
}

// ---------------------------------------------------------------------------
// Flash-attention (fp32, causal), f32x2-packed inner GEMM loops.
// One block = 64 query rows of one (b,h). Qt/K^T/P^T tiles transposed so both
// inner loops are LDS.128 + packed FMA2. 48KB static smem.
// Masked tiles (kb > qb) skipped; -10000 bias underflows to exact 0.
// ---------------------------------------------------------------------------
__global__ __launch_bounds__(256) void attn_kernel()
{
    const int qb = blockIdx.x;          // 0..15
    const int bh = blockIdx.y;          // 0..127
    const int bb = bh >> 4;
    const int hh = bh & 15;

    const float* Qg = g_q + (size_t)bh * NS * DH + (size_t)qb * 64 * DH;
    const float* Kg = g_k + (size_t)bh * NS * DH;
    const float* Vg = g_v + (size_t)bh * NS * DH;

    __shared__ float Qt[64 * 64];       // [d][r]
    __shared__ float KPt[64 * 64];      // K as [d][c], then reused as P^T [k][r]
    __shared__ float Vs[64 * 64];       // [k][d]

    const int tid = threadIdx.x;
    const int tx = tid & 15, ty = tid >> 4;

    for (int f = tid; f < 1024; f += 256) {
        const int r  = f >> 4;
        const int c4 = (f & 15) << 2;
        float4 v = *(const float4*)(Qg + (r << 6) + c4);
        Qt[(c4 + 0) * 64 + r] = v.x;
        Qt[(c4 + 1) * 64 + r] = v.y;
        Qt[(c4 + 2) * 64 + r] = v.z;
        Qt[(c4 + 3) * 64 + r] = v.w;
    }

    float m_i[4], l_i[4];
    unsigned long long o2[4][2];        // packed output accumulators (pairs on j)
    #pragma unroll
    for (int i = 0; i < 4; i++) {
        m_i[i] = -1e30f; l_i[i] = 0.f;
        o2[i][0] = 0ull; o2[i][1] = 0ull;
    }

    for (int kb = 0; kb <= qb; kb++) {
        __syncthreads();
        const float* Ktile = Kg + (size_t)kb * 64 * DH;
        const float* Vtile = Vg + (size_t)kb * 64 * DH;
        for (int f = tid; f < 1024; f += 256) {
            const int r  = f >> 4;
            const int c4 = (f & 15) << 2;
            float4 kv = *(const float4*)(Ktile + (r << 6) + c4);
            KPt[(c4 + 0) * 64 + r] = kv.x;
            KPt[(c4 + 1) * 64 + r] = kv.y;
            KPt[(c4 + 2) * 64 + r] = kv.z;
            KPt[(c4 + 3) * 64 + r] = kv.w;
            float4 vv = *(const float4*)(Vtile + (r << 6) + c4);
            *(float4*)&Vs[(r << 6) + c4] = vv;
        }
        __syncthreads();

        // S = Q K^T (packed pairs along the 4 key columns)
        unsigned long long s2[4][2];
        #pragma unroll
        for (int i = 0; i < 4; i++) { s2[i][0] = 0ull; s2[i][1] = 0ull; }

        #pragma unroll 4
        for (int d = 0; d < 64; d++) {
            float4 qv = *(const float4*)&Qt[(d << 6) + (ty << 2)];
            ulonglong2 kp = *(const ulonglong2*)&KPt[(d << 6) + (tx << 2)];
            float qf[4] = {qv.x, qv.y, qv.z, qv.w};
            #pragma unroll
            for (int i = 0; i < 4; i++) {
                unsigned long long aq;
                PACK2(aq, qf[i]);
                FMA2(s2[i][0], aq, kp.x);
                FMA2(s2[i][1], aq, kp.y);
            }
        }

        float s[4][4];
        #pragma unroll
        for (int i = 0; i < 4; i++) {
            uint32_t u0, u1, u2, u3;
            UNPK2(u0, u1, s2[i][0]);
            UNPK2(u2, u3, s2[i][1]);
            s[i][0] = __uint_as_float(u0); s[i][1] = __uint_as_float(u1);
            s[i][2] = __uint_as_float(u2); s[i][3] = __uint_as_float(u3);
        }

        // scale, causal mask, online softmax (16 lanes share each row group)
        float p[4][4];
        #pragma unroll
        for (int i = 0; i < 4; i++) {
            float mloc = -1e30f;
            #pragma unroll
            for (int j = 0; j < 4; j++) {
                float v = s[i][j] * 0.125f;   // 1/sqrt(64)
                if (kb == qb && (tx * 4 + j) > (ty * 4 + i)) v = -1e30f;
                s[i][j] = v;
                mloc = fmaxf(mloc, v);
            }
            mloc = fmaxf(mloc, __shfl_xor_sync(0xffffffffu, mloc, 1));
            mloc = fmaxf(mloc, __shfl_xor_sync(0xffffffffu, mloc, 2));
            mloc = fmaxf(mloc, __shfl_xor_sync(0xffffffffu, mloc, 4));
            mloc = fmaxf(mloc, __shfl_xor_sync(0xffffffffu, mloc, 8));
            const float mn = fmaxf(m_i[i], mloc);
            const float sc = __expf(m_i[i] - mn);
            float rs = 0.f;
            #pragma unroll
            for (int j = 0; j < 4; j++) {
                p[i][j] = __expf(s[i][j] - mn);
                rs += p[i][j];
            }
            rs += __shfl_xor_sync(0xffffffffu, rs, 1);
            rs += __shfl_xor_sync(0xffffffffu, rs, 2);
            rs += __shfl_xor_sync(0xffffffffu, rs, 4);
            rs += __shfl_xor_sync(0xffffffffu, rs, 8);
            l_i[i] = l_i[i] * sc + rs;
            m_i[i] = mn;
            unsigned long long sc2;
            PACK2(sc2, sc);
            MUL2(o2[i][0], sc2);
            MUL2(o2[i][1], sc2);
        }

        __syncthreads();                 // done reading K before P^T overwrite
        #pragma unroll
        for (int i = 0; i < 4; i++)
            #pragma unroll
            for (int j = 0; j < 4; j++)
                KPt[(tx * 4 + j) * 64 + ty * 4 + i] = p[i][j];  // P^T [k][r]
        __syncthreads();

        // O += P V (packed pairs along the 4 headdim columns)
        #pragma unroll 4
        for (int k = 0; k < 64; k++) {
            float4 pv = *(const float4*)&KPt[(k << 6) + (ty << 2)];
            ulonglong2 vp = *(const ulonglong2*)&Vs[(k << 6) + (tx << 2)];
            float pf[4] = {pv.x, pv.y, pv.z, pv.w};
            #pragma unroll
            for (int i = 0; i < 4; i++) {
                unsigned long long ap;
                PACK2(ap, pf[i]);
                FMA2(o2[i][0], ap, vp.x);
                FMA2(o2[i][1], ap, vp.y);
            }
        }
    }

    // write merged-head output into g_a [B,S,NX]
    float* outp = g_a + ((size_t)bb * NS + qb * 64) * NXD + hh * 64;
    #pragma unroll
    for (int i = 0; i < 4; i++) {
        const float inv = 1.f / l_i[i];
        uint32_t u0, u1, u2, u3;
        UNPK2(u0, u1, o2[i][0]);
        UNPK2(u2, u3, o2[i][1]);
        float4 o;
        o.x = __uint_as_float(u0) * inv;
        o.y = __uint_as_float(u1) * inv;
        o.z = __uint_as_float(u2) * inv;
        o.w = __uint_as_float(u3) * inv;
        *(float4*)&outp[(size_t)(ty * 4 + i) * NXD + tx * 4] = o;
    }
}

// ---------------------------------------------------------------------------
extern "C" void kernel_launch(void* const* d_in, const int* in_sizes, int n_in,
                              void* d_out, int out_size)
{
    (void)in_sizes; (void)n_in; (void)out_size;
    const float* x        = (const float*)d_in[0];
    const float* query    = (const float*)d_in[1];
    const float* c_attn_w = (const float*)d_in[2];
    const float* c_attn_b = (const float*)d_in[3];
    const float* c_proj_w = (const float*)d_in[4];
    const float* c_proj_b = (const float*)d_in[5];
    float* out = (float*)d_out;

    qkv_gemm<<<dim3(48, 64), 256>>>(x, query, c_attn_w, c_attn_b);
    attn_kernel<<<dim3(16, 128), 256>>>();
    proj_gemm<<<dim3(16, 64), 256>>>(c_proj_w, c_proj_b, out);
}

// round 5
// speedup vs baseline: 1.2955x; 1.2955x over previous
#include <cuda_runtime.h>
#include <cuda_bf16.h>
#include <cstdint>

#define NB  8
#define NS  1024
#define NXD 1024
#define NH  16
#define DH  64

// ---------------- bf16 hi/lo scratch planes (device globals) ----------------
__device__ __align__(16) __nv_bfloat16 g_xh[NB*NS*NXD], g_xl[NB*NS*NXD];
__device__ __align__(16) __nv_bfloat16 g_qh[NB*NS*NXD], g_ql[NB*NS*NXD];
__device__ __align__(16) __nv_bfloat16 g_wh[NXD*3*NXD], g_wl[NXD*3*NXD];
__device__ __align__(16) __nv_bfloat16 g_ph[NXD*NXD],   g_pl[NXD*NXD];
__device__ __align__(16) __nv_bfloat16 gQh[NB*NH*NS*DH], gQl[NB*NH*NS*DH];
__device__ __align__(16) __nv_bfloat16 gKh[NB*NH*NS*DH], gKl[NB*NH*NS*DH];
__device__ __align__(16) __nv_bfloat16 gVh[NB*NH*NS*DH], gVl[NB*NH*NS*DH];
__device__ __align__(16) __nv_bfloat16 gAh[NB*NS*NXD],   gAl[NB*NS*NXD];

// ---------------- helpers ----------------
__device__ __forceinline__ uint32_t s2u(const void* p) {
    return (uint32_t)__cvta_generic_to_shared(p);
}
__device__ __forceinline__ void bsplit(float x, __nv_bfloat16& h, __nv_bfloat16& l) {
    h = __float2bfloat16_rn(x);
    l = __float2bfloat16_rn(x - __bfloat162float(h));
}
__device__ __forceinline__ uint32_t bpack(__nv_bfloat16 a, __nv_bfloat16 b) {
    __nv_bfloat162 t = __halves2bfloat162(a, b);
    return *reinterpret_cast<uint32_t*>(&t);
}

#define LDSM_X4(d0,d1,d2,d3,a) \
    asm volatile("ldmatrix.sync.aligned.m8n8.x4.shared.b16 {%0,%1,%2,%3},[%4];" \
        : "=r"(d0),"=r"(d1),"=r"(d2),"=r"(d3) : "r"(a))
#define LDSM_X4T(d0,d1,d2,d3,a) \
    asm volatile("ldmatrix.sync.aligned.m8n8.x4.trans.shared.b16 {%0,%1,%2,%3},[%4];" \
        : "=r"(d0),"=r"(d1),"=r"(d2),"=r"(d3) : "r"(a))

__device__ __forceinline__ void mma_bf16(float* c, const uint32_t* a,
                                         uint32_t b0, uint32_t b1) {
    asm volatile(
        "mma.sync.aligned.m16n8k16.row.col.f32.bf16.bf16.f32 "
        "{%0,%1,%2,%3},{%4,%5,%6,%7},{%8,%9},{%0,%1,%2,%3};"
        : "+f"(c[0]), "+f"(c[1]), "+f"(c[2]), "+f"(c[3])
        : "r"(a[0]), "r"(a[1]), "r"(a[2]), "r"(a[3]), "r"(b0), "r"(b1));
}

// ---------------- split kernel: fp32 -> bf16 hi/lo planes ----------------
__global__ void split_kernel(const float4* __restrict__ src, int which, int n4) {
    __nv_bfloat16 *h, *l;
    if      (which == 0) { h = g_xh; l = g_xl; }
    else if (which == 1) { h = g_qh; l = g_ql; }
    else if (which == 2) { h = g_wh; l = g_wl; }
    else                 { h = g_ph; l = g_pl; }
    for (int i = blockIdx.x * blockDim.x + threadIdx.x; i < n4;
         i += gridDim.x * blockDim.x) {
        float4 v = src[i];
        __nv_bfloat16 h0,l0,h1,l1,h2,l2,h3,l3;
        bsplit(v.x, h0, l0); bsplit(v.y, h1, l1);
        bsplit(v.z, h2, l2); bsplit(v.w, h3, l3);
        uint2 ph; ph.x = bpack(h0, h1); ph.y = bpack(h2, h3);
        uint2 pl; pl.x = bpack(l0, l1); pl.y = bpack(l2, l3);
        *(uint2*)&h[(size_t)i * 4] = ph;
        *(uint2*)&l[(size_t)i * 4] = pl;
    }
}

// ---------------------------------------------------------------------------
// bf16x3 GEMM mainloop. Block 128(M) x 128(N), BK=32, 256 threads, 8 warps
// (2Mx4N), warp 64x32 = 4 m16-frags x 4 n8-frags. Per k16-step:
// acc += Ah*Bh + Ah*Bl + Al*Bh  (48 MMAs, 12 LDSM).
// A row-major [.,1024] bf16 planes; B row-major [1024, ldb] bf16 planes.
// ---------------------------------------------------------------------------
__device__ __forceinline__ void gemm_main(
    const __nv_bfloat16* __restrict__ Agh, const __nv_bfloat16* __restrict__ Agl,
    const __nv_bfloat16* __restrict__ Bgh, const __nv_bfloat16* __restrict__ Bgl,
    int ldb, int m0, int n0,
    __nv_bfloat16* Ash, __nv_bfloat16* Asl,
    __nv_bfloat16* Bsh, __nv_bfloat16* Bsl,
    float (&acc)[4][4][4])
{
    const int tid  = threadIdx.x;
    const int lane = tid & 31;
    const int wid  = tid >> 5;
    const int warpM = wid >> 2;          // 0..1
    const int warpN = wid & 3;           // 0..3

    #pragma unroll
    for (int mt = 0; mt < 4; mt++)
        #pragma unroll
        for (int nf = 0; nf < 4; nf++)
            #pragma unroll
            for (int r = 0; r < 4; r++) acc[mt][nf][r] = 0.f;

    const int ar = tid >> 1;             // 0..127
    const int ac = (tid & 1) << 3;       // 0,8 (+16 second chunk)
    const int br = tid >> 4;             // 0..15 (+16 second)
    const int bc = (tid & 15) << 3;      // 0..120

    const __nv_bfloat16* pAh = Agh + (size_t)(m0 + ar) * 1024 + ac;
    const __nv_bfloat16* pAl = Agl + (size_t)(m0 + ar) * 1024 + ac;
    const __nv_bfloat16* pBh = Bgh + (size_t)br * ldb + n0 + bc;
    const __nv_bfloat16* pBl = Bgl + (size_t)br * ldb + n0 + bc;

    uint4 rah0 = *(const uint4*)pAh;
    uint4 rah1 = *(const uint4*)(pAh + 16);
    uint4 ral0 = *(const uint4*)pAl;
    uint4 ral1 = *(const uint4*)(pAl + 16);
    uint4 rbh0 = *(const uint4*)pBh;
    uint4 rbh1 = *(const uint4*)(pBh + (size_t)16 * ldb);
    uint4 rbl0 = *(const uint4*)pBl;
    uint4 rbl1 = *(const uint4*)(pBl + (size_t)16 * ldb);

    for (int k0 = 0; k0 < 1024; k0 += 32) {
        __syncthreads();
        *(uint4*)&Ash[ar * 40 + ac]        = rah0;
        *(uint4*)&Ash[ar * 40 + ac + 16]   = rah1;
        *(uint4*)&Asl[ar * 40 + ac]        = ral0;
        *(uint4*)&Asl[ar * 40 + ac + 16]   = ral1;
        *(uint4*)&Bsh[br * 136 + bc]        = rbh0;
        *(uint4*)&Bsh[(br + 16) * 136 + bc] = rbh1;
        *(uint4*)&Bsl[br * 136 + bc]        = rbl0;
        *(uint4*)&Bsl[(br + 16) * 136 + bc] = rbl1;
        __syncthreads();

        if (k0 + 32 < 1024) {
            rah0 = *(const uint4*)(pAh + k0 + 32);
            rah1 = *(const uint4*)(pAh + k0 + 48);
            ral0 = *(const uint4*)(pAl + k0 + 32);
            ral1 = *(const uint4*)(pAl + k0 + 48);
            rbh0 = *(const uint4*)(pBh + (size_t)(k0 + 32) * ldb);
            rbh1 = *(const uint4*)(pBh + (size_t)(k0 + 48) * ldb);
            rbl0 = *(const uint4*)(pBl + (size_t)(k0 + 32) * ldb);
            rbl1 = *(const uint4*)(pBl + (size_t)(k0 + 48) * ldb);
        }

        #pragma unroll
        for (int ks = 0; ks < 2; ks++) {
            // A fragments (hi + lo)
            uint32_t ah[4][4], al[4][4];
            const int arow_f = (lane & 15);
            const int acol_f = ks * 16 + ((lane >> 4) << 3);
            #pragma unroll
            for (int mt = 0; mt < 4; mt++) {
                const int row = warpM * 64 + mt * 16 + arow_f;
                uint32_t ad = s2u(&Ash[row * 40 + acol_f]);
                LDSM_X4(ah[mt][0], ah[mt][1], ah[mt][2], ah[mt][3], ad);
                uint32_t ad2 = s2u(&Asl[row * 40 + acol_f]);
                LDSM_X4(al[mt][0], al[mt][1], al[mt][2], al[mt][3], ad2);
            }
            // B fragments (hi + lo), trans from [k][n]
            uint32_t bh[4][2], bl[4][2];
            const int brow_f = ks * 16 + (lane & 7) + ((lane >> 3) & 1) * 8;
            #pragma unroll
            for (int pp = 0; pp < 2; pp++) {
                const int col = warpN * 32 + pp * 16 + ((lane >> 4) << 3);
                uint32_t bd = s2u(&Bsh[brow_f * 136 + col]);
                LDSM_X4T(bh[2*pp][0], bh[2*pp][1], bh[2*pp+1][0], bh[2*pp+1][1], bd);
                uint32_t bd2 = s2u(&Bsl[brow_f * 136 + col]);
                LDSM_X4T(bl[2*pp][0], bl[2*pp][1], bl[2*pp+1][0], bl[2*pp+1][1], bd2);
            }
            #pragma unroll
            for (int mt = 0; mt < 4; mt++)
                #pragma unroll
                for (int nf = 0; nf < 4; nf++) {
                    mma_bf16(acc[mt][nf], ah[mt], bh[nf][0], bh[nf][1]);
                    mma_bf16(acc[mt][nf], ah[mt], bl[nf][0], bl[nf][1]);
                    mma_bf16(acc[mt][nf], al[mt], bh[nf][0], bh[nf][1]);
                }
        }
    }
}

// ---------------------------------------------------------------------------
// QKV projection: [8192,3072] = A @ W + b; scattered to q/k/v bf16 hi/lo
// planes in [B,H,S,HD] layout. q region pre-scaled by 1/sqrt(HD).
// ---------------------------------------------------------------------------
__global__ __launch_bounds__(256) void qkv_gemm(const float* __restrict__ bias)
{
    __shared__ __align__(16) __nv_bfloat16 Ash[128 * 40], Asl[128 * 40];
    __shared__ __align__(16) __nv_bfloat16 Bsh[32 * 136], Bsl[32 * 136];

    const int n0 = blockIdx.x * 128;
    const int m0 = blockIdx.y * 128;
    const int region = n0 >> 10;              // 0=q, 1=k, 2=v

    const __nv_bfloat16* Agh = (region == 0) ? g_qh : g_xh;
    const __nv_bfloat16* Agl = (region == 0) ? g_ql : g_xl;
    __nv_bfloat16* dh = (region == 0) ? gQh : ((region == 1) ? gKh : gVh);
    __nv_bfloat16* dl = (region == 0) ? gQl : ((region == 1) ? gKl : gVl);
    const float scale = (region == 0) ? 0.125f : 1.0f;

    float acc[4][4][4];
    gemm_main(Agh, Agl, g_wh, g_wl, 3072, m0, n0, Ash, Asl, Bsh, Bsl, acc);

    const int lane = threadIdx.x & 31;
    const int wid  = threadIdx.x >> 5;
    const int warpM = wid >> 2, warpN = wid & 3;
    const int g = lane >> 2, tg = lane & 3;

    #pragma unroll
    for (int mt = 0; mt < 4; mt++) {
        #pragma unroll
        for (int nf = 0; nf < 4; nf++) {
            const int col = n0 + warpN * 32 + nf * 8 + 2 * tg;
            const int nn = col & 1023;
            const int hh = nn >> 6, dd = nn & 63;
            const float b0v = bias[col], b1v = bias[col + 1];
            #pragma unroll
            for (int half = 0; half < 2; half++) {
                const int row = m0 + warpM * 64 + mt * 16 + g + 8 * half;
                const int bb = row >> 10, ss = row & 1023;
                float v0 = (acc[mt][nf][2*half + 0] + b0v) * scale;
                float v1 = (acc[mt][nf][2*half + 1] + b1v) * scale;
                __nv_bfloat16 h0, l0, h1, l1;
                bsplit(v0, h0, l0); bsplit(v1, h1, l1);
                const size_t o = ((size_t)((bb * NH + hh) * NS + ss)) * DH + dd;
                *(uint32_t*)&dh[o] = bpack(h0, h1);
                *(uint32_t*)&dl[o] = bpack(l0, l1);
            }
        }
    }
}

// ---------------------------------------------------------------------------
// Output projection: out[8192,1024] = attn_out @ Wp + bp (fp32 out)
// ---------------------------------------------------------------------------
__global__ __launch_bounds__(256) void proj_gemm(const float* __restrict__ bias,
                                                 float* __restrict__ out)
{
    __shared__ __align__(16) __nv_bfloat16 Ash[128 * 40], Asl[128 * 40];
    __shared__ __align__(16) __nv_bfloat16 Bsh[32 * 136], Bsl[32 * 136];

    const int n0 = blockIdx.x * 128;
    const int m0 = blockIdx.y * 128;

    float acc[4][4][4];
    gemm_main(gAh, gAl, g_ph, g_pl, 1024, m0, n0, Ash, Asl, Bsh, Bsl, acc);

    const int lane = threadIdx.x & 31;
    const int wid  = threadIdx.x >> 5;
    const int warpM = wid >> 2, warpN = wid & 3;
    const int g = lane >> 2, tg = lane & 3;

    #pragma unroll
    for (int mt = 0; mt < 4; mt++) {
        #pragma unroll
        for (int nf = 0; nf < 4; nf++) {
            const int col = n0 + warpN * 32 + nf * 8 + 2 * tg;
            const float b0v = bias[col], b1v = bias[col + 1];
            #pragma unroll
            for (int half = 0; half < 2; half++) {
                const int row = m0 + warpM * 64 + mt * 16 + g + 8 * half;
                float2 st;
                st.x = acc[mt][nf][2*half + 0] + b0v;
                st.y = acc[mt][nf][2*half + 1] + b1v;
                *(float2*)&out[(size_t)row * NXD + col] = st;
            }
        }
    }
}

// ---------------------------------------------------------------------------
// Flash attention, bf16x3 tensor-core. Block = 128 q-rows of one (b,h),
// 8 warps, warp = 16-row strip. Q frags register-resident; K/V hi/lo tiles
// in smem. P re-packed from S C-frags into A-frags with bf16 hi/lo split.
// Output written as bf16 hi/lo planes for the projection GEMM.
// ---------------------------------------------------------------------------
__global__ __launch_bounds__(256) void attn_kernel()
{
    const int qb2 = blockIdx.x;          // 0..7  (128-row q block)
    const int bh  = blockIdx.y;          // 0..127
    const int bb = bh >> 4, hh = bh & 15;
    const size_t off = (size_t)bh * NS * DH;

    __shared__ __align__(16) __nv_bfloat16 SM[4 * 64 * 72];
    __nv_bfloat16* Ksh = SM;             // [64][72]
    __nv_bfloat16* Ksl = SM + 4608;
    __nv_bfloat16* Vsh = SM + 9216;
    __nv_bfloat16* Vsl = SM + 13824;

    const int tid  = threadIdx.x;
    const int lane = tid & 31;
    const int w    = tid >> 5;           // 0..7
    const int g = lane >> 2, tg = lane & 3;
    const int r0 = qb2 * 128 + w * 16;   // warp strip global row base

    // ---- load Q fragments into registers (hi then lo, staged via smem) ----
    uint32_t qfh[4][4], qfl[4][4];
    {
        const __nv_bfloat16* srcs[2] = { gQh + off + (size_t)(qb2 * 128) * DH,
                                         gQl + off + (size_t)(qb2 * 128) * DH };
        #pragma unroll
        for (int ph = 0; ph < 2; ph++) {
            const __nv_bfloat16* src = srcs[ph];
            for (int i = tid; i < 1024; i += 256) {
                const int r = i >> 3, c = (i & 7) << 3;
                *(uint4*)&SM[r * 72 + c] = *(const uint4*)&src[(size_t)r * 64 + c];
            }
            __syncthreads();
            const int qrow = w * 16 + (lane & 15);
            #pragma unroll
            for (int ks = 0; ks < 4; ks++) {
                uint32_t ad = s2u(&SM[qrow * 72 + ks * 16 + ((lane >> 4) << 3)]);
                if (ph == 0) { LDSM_X4(qfh[ks][0], qfh[ks][1], qfh[ks][2], qfh[ks][3], ad); }
                else         { LDSM_X4(qfl[ks][0], qfl[ks][1], qfl[ks][2], qfl[ks][3], ad); }
            }
            __syncthreads();
        }
    }

    float O[8][4];
    #pragma unroll
    for (int nf = 0; nf < 8; nf++)
        #pragma unroll
        for (int r = 0; r < 4; r++) O[nf][r] = 0.f;
    float m0_ = -1e30f, m1_ = -1e30f, l0_ = 0.f, l1_ = 0.f;

    const __nv_bfloat16* Kh_g = gKh + off;
    const __nv_bfloat16* Kl_g = gKl + off;
    const __nv_bfloat16* Vh_g = gVh + off;
    const __nv_bfloat16* Vl_g = gVl + off;

    const int kbmax = 2 * qb2 + 2;
    for (int kb = 0; kb < kbmax; kb++) {
        __syncthreads();
        const size_t tile = (size_t)kb * 64 * DH;
        for (int i = tid; i < 512; i += 256) {
            const int r = i >> 3, c = (i & 7) << 3;
            const size_t gi = tile + (size_t)r * 64 + c;
            *(uint4*)&Ksh[r * 72 + c] = *(const uint4*)&Kh_g[gi];
            *(uint4*)&Ksl[r * 72 + c] = *(const uint4*)&Kl_g[gi];
            *(uint4*)&Vsh[r * 72 + c] = *(const uint4*)&Vh_g[gi];
            *(uint4*)&Vsl[r * 72 + c] = *(const uint4*)&Vl_g[gi];
        }
        __syncthreads();

        if (kb * 64 > r0 + 15) continue;     // fully masked for this warp

        // ---- S = Q K^T ----
        float S[8][4];
        #pragma unroll
        for (int nf = 0; nf < 8; nf++)
            #pragma unroll
            for (int r = 0; r < 4; r++) S[nf][r] = 0.f;

        #pragma unroll
        for (int ks = 0; ks < 4; ks++) {
            uint32_t bhf[8][2], blf[8][2];
            const int nrow = (lane & 7) + ((lane >> 4) << 3);
            const int kcol = ks * 16 + ((lane >> 3) & 1) * 8;
            #pragma unroll
            for (int pp = 0; pp < 4; pp++) {
                uint32_t ad = s2u(&Ksh[(pp * 16 + nrow) * 72 + kcol]);
                LDSM_X4(bhf[2*pp][0], bhf[2*pp][1], bhf[2*pp+1][0], bhf[2*pp+1][1], ad);
                uint32_t ad2 = s2u(&Ksl[(pp * 16 + nrow) * 72 + kcol]);
                LDSM_X4(blf[2*pp][0], blf[2*pp][1], blf[2*pp+1][0], blf[2*pp+1][1], ad2);
            }
            #pragma unroll
            for (int nf = 0; nf < 8; nf++) {
                mma_bf16(S[nf], qfh[ks], bhf[nf][0], bhf[nf][1]);
                mma_bf16(S[nf], qfh[ks], blf[nf][0], blf[nf][1]);
                mma_bf16(S[nf], qfl[ks], bhf[nf][0], bhf[nf][1]);
            }
        }

        // ---- causal mask (diagonal-overlap tiles only) ----
        if (kb * 64 + 63 > r0) {
            #pragma unroll
            for (int nf = 0; nf < 8; nf++) {
                #pragma unroll
                for (int e = 0; e < 4; e++) {
                    const int j = kb * 64 + nf * 8 + 2 * tg + (e & 1);
                    const int rr = r0 + g + ((e >= 2) ? 8 : 0);
                    if (j > rr) S[nf][e] = -1e30f;
                }
            }
        }

        // ---- online softmax (rows g and g+8; quad-reduce over tg) ----
        float mx0 = -1e30f, mx1 = -1e30f;
        #pragma unroll
        for (int nf = 0; nf < 8; nf++) {
            mx0 = fmaxf(mx0, fmaxf(S[nf][0], S[nf][1]));
            mx1 = fmaxf(mx1, fmaxf(S[nf][2], S[nf][3]));
        }
        mx0 = fmaxf(mx0, __shfl_xor_sync(0xffffffffu, mx0, 1));
        mx0 = fmaxf(mx0, __shfl_xor_sync(0xffffffffu, mx0, 2));
        mx1 = fmaxf(mx1, __shfl_xor_sync(0xffffffffu, mx1, 1));
        mx1 = fmaxf(mx1, __shfl_xor_sync(0xffffffffu, mx1, 2));
        const float mn0 = fmaxf(m0_, mx0), mn1 = fmaxf(m1_, mx1);
        const float sc0 = __expf(m0_ - mn0), sc1 = __expf(m1_ - mn1);
        float rs0 = 0.f, rs1 = 0.f;
        #pragma unroll
        for (int nf = 0; nf < 8; nf++) {
            S[nf][0] = __expf(S[nf][0] - mn0);
            S[nf][1] = __expf(S[nf][1] - mn0);
            S[nf][2] = __expf(S[nf][2] - mn1);
            S[nf][3] = __expf(S[nf][3] - mn1);
            rs0 += S[nf][0] + S[nf][1];
            rs1 += S[nf][2] + S[nf][3];
        }
        rs0 += __shfl_xor_sync(0xffffffffu, rs0, 1);
        rs0 += __shfl_xor_sync(0xffffffffu, rs0, 2);
        rs1 += __shfl_xor_sync(0xffffffffu, rs1, 1);
        rs1 += __shfl_xor_sync(0xffffffffu, rs1, 2);
        l0_ = l0_ * sc0 + rs0;  l1_ = l1_ * sc1 + rs1;
        m0_ = mn0;  m1_ = mn1;
        #pragma unroll
        for (int nf = 0; nf < 8; nf++) {
            O[nf][0] *= sc0; O[nf][1] *= sc0;
            O[nf][2] *= sc1; O[nf][3] *= sc1;
        }

        // ---- O += P V ----
        #pragma unroll
        for (int ks = 0; ks < 4; ks++) {
            // pack P A-fragments (hi/lo) from S frags 2ks, 2ks+1
            uint32_t pah[4], pal[4];
            {
                __nv_bfloat16 h0,l0,h1,l1;
                bsplit(S[2*ks][0], h0, l0); bsplit(S[2*ks][1], h1, l1);
                pah[0] = bpack(h0, h1); pal[0] = bpack(l0, l1);
                bsplit(S[2*ks][2], h0, l0); bsplit(S[2*ks][3], h1, l1);
                pah[1] = bpack(h0, h1); pal[1] = bpack(l0, l1);
                bsplit(S[2*ks+1][0], h0, l0); bsplit(S[2*ks+1][1], h1, l1);
                pah[2] = bpack(h0, h1); pal[2] = bpack(l0, l1);
                bsplit(S[2*ks+1][2], h0, l0); bsplit(S[2*ks+1][3], h1, l1);
                pah[3] = bpack(h0, h1); pal[3] = bpack(l0, l1);
            }
            uint32_t vhf[8][2], vlf[8][2];
            const int krow = ks * 16 + (lane & 7) + ((lane >> 3) & 1) * 8;
            const int ncol = ((lane >> 4) << 3);
            #pragma unroll
            for (int pp = 0; pp < 4; pp++) {
                uint32_t ad = s2u(&Vsh[krow * 72 + pp * 16 + ncol]);
                LDSM_X4T(vhf[2*pp][0], vhf[2*pp][1], vhf[2*pp+1][0], vhf[2*pp+1][1], ad);
                uint32_t ad2 = s2u(&Vsl[krow * 72 + pp * 16 + ncol]);
                LDSM_X4T(vlf[2*pp][0], vlf[2*pp][1], vlf[2*pp+1][0], vlf[2*pp+1][1], ad2);
            }
            #pragma unroll
            for (int nf = 0; nf < 8; nf++) {
                mma_bf16(O[nf], pah, vhf[nf][0], vhf[nf][1]);
                mma_bf16(O[nf], pah, vlf[nf][0], vlf[nf][1]);
                mma_bf16(O[nf], pal, vhf[nf][0], vhf[nf][1]);
            }
        }
    }

    // ---- epilogue: O/l -> bf16 hi/lo planes of attn output [B,S,NX] ----
    const float inv0 = 1.f / l0_, inv1 = 1.f / l1_;
    const int row0 = r0 + g, row1 = r0 + g + 8;
    const size_t base0 = ((size_t)bb * NS + row0) * NXD + hh * 64;
    const size_t base1 = ((size_t)bb * NS + row1) * NXD + hh * 64;
    #pragma unroll
    for (int nf = 0; nf < 8; nf++) {
        const int d = nf * 8 + 2 * tg;
        __nv_bfloat16 h0,l0,h1,l1;
        bsplit(O[nf][0] * inv0, h0, l0); bsplit(O[nf][1] * inv0, h1, l1);
        *(uint32_t*)&gAh[base0 + d] = bpack(h0, h1);
        *(uint32_t*)&gAl[base0 + d] = bpack(l0, l1);
        bsplit(O[nf][2] * inv1, h0, l0); bsplit(O[nf][3] * inv1, h1, l1);
        *(uint32_t*)&gAh[base1 + d] = bpack(h0, h1);
        *(uint32_t*)&gAl[base1 + d] = bpack(l0, l1);
    }
}

// ---------------------------------------------------------------------------
extern "C" void kernel_launch(void* const* d_in, const int* in_sizes, int n_in,
                              void* d_out, int out_size)
{
    (void)in_sizes; (void)n_in; (void)out_size;
    const float* x        = (const float*)d_in[0];
    const float* query    = (const float*)d_in[1];
    const float* c_attn_w = (const float*)d_in[2];
    const float* c_attn_b = (const float*)d_in[3];
    const float* c_proj_w = (const float*)d_in[4];
    const float* c_proj_b = (const float*)d_in[5];
    float* out = (float*)d_out;

    split_kernel<<<2048, 256>>>((const float4*)x,        0, NB*NS*NXD/4);
    split_kernel<<<2048, 256>>>((const float4*)query,    1, NB*NS*NXD/4);
    split_kernel<<<2048, 256>>>((const float4*)c_attn_w, 2, NXD*3*NXD/4);
    split_kernel<<<1024, 256>>>((const float4*)c_proj_w, 3, NXD*NXD/4);

    qkv_gemm<<<dim3(24, 64), 256>>>(c_attn_b);
    attn_kernel<<<dim3(8, 128), 256>>>();
    proj_gemm<<<dim3(8, 64), 256>>>(c_proj_b, out);
}

// round 10
// speedup vs baseline: 1.9162x; 1.4791x over previous
#include <cuda_runtime.h>
#include <cuda_bf16.h>
#include <cstdint>

#define NB  8
#define NS  1024
#define NXD 1024
#define NH  16
#define DH  64

// ---------------- bf16 hi/lo scratch planes (device globals) ----------------
__device__ __align__(16) __nv_bfloat16 g_xh[NB*NS*NXD], g_xl[NB*NS*NXD];
__device__ __align__(16) __nv_bfloat16 g_qh[NB*NS*NXD], g_ql[NB*NS*NXD];
__device__ __align__(16) __nv_bfloat16 g_wh[NXD*3*NXD], g_wl[NXD*3*NXD];
__device__ __align__(16) __nv_bfloat16 g_ph[NXD*NXD],   g_pl[NXD*NXD];
__device__ __align__(16) __nv_bfloat16 gQh[NB*NH*NS*DH], gQl[NB*NH*NS*DH];
__device__ __align__(16) __nv_bfloat16 gKh[NB*NH*NS*DH], gKl[NB*NH*NS*DH];
__device__ __align__(16) __nv_bfloat16 gVh[NB*NH*NS*DH], gVl[NB*NH*NS*DH];
__device__ __align__(16) __nv_bfloat16 gAh[NB*NS*NXD],   gAl[NB*NS*NXD];

// ---------------- helpers ----------------
__device__ __forceinline__ uint32_t s2u(const void* p) {
    return (uint32_t)__cvta_generic_to_shared(p);
}
__device__ __forceinline__ void bsplit(float x, __nv_bfloat16& h, __nv_bfloat16& l) {
    h = __float2bfloat16_rn(x);
    l = __float2bfloat16_rn(x - __bfloat162float(h));
}
__device__ __forceinline__ uint32_t bpack(__nv_bfloat16 a, __nv_bfloat16 b) {
    __nv_bfloat162 t = __halves2bfloat162(a, b);
    return *reinterpret_cast<uint32_t*>(&t);
}

#define LDSM_X4(d0,d1,d2,d3,a) \
    asm volatile("ldmatrix.sync.aligned.m8n8.x4.shared.b16 {%0,%1,%2,%3},[%4];" \
        : "=r"(d0),"=r"(d1),"=r"(d2),"=r"(d3) : "r"(a))
#define LDSM_X4T(d0,d1,d2,d3,a) \
    asm volatile("ldmatrix.sync.aligned.m8n8.x4.trans.shared.b16 {%0,%1,%2,%3},[%4];" \
        : "=r"(d0),"=r"(d1),"=r"(d2),"=r"(d3) : "r"(a))

__device__ __forceinline__ void mma_bf16(float* c, const uint32_t* a,
                                         uint32_t b0, uint32_t b1) {
    asm volatile(
        "mma.sync.aligned.m16n8k16.row.col.f32.bf16.bf16.f32 "
        "{%0,%1,%2,%3},{%4,%5,%6,%7},{%8,%9},{%0,%1,%2,%3};"
        : "+f"(c[0]), "+f"(c[1]), "+f"(c[2]), "+f"(c[3])
        : "r"(a[0]), "r"(a[1]), "r"(a[2]), "r"(a[3]), "r"(b0), "r"(b1));
}

__device__ __forceinline__ void cpa16(uint32_t dst, const void* src) {
    asm volatile("cp.async.cg.shared.global [%0],[%1],16;" :: "r"(dst), "l"(src));
}
#define CP_COMMIT() asm volatile("cp.async.commit_group;")
#define CP_WAIT1()  asm volatile("cp.async.wait_group 1;")
#define CP_WAIT0()  asm volatile("cp.async.wait_group 0;")

// ---------------- split kernel: fp32 -> bf16 hi/lo planes ----------------
__global__ void split_kernel(const float4* __restrict__ src, int which, int n4) {
    __nv_bfloat16 *h, *l;
    if      (which == 0) { h = g_xh; l = g_xl; }
    else if (which == 1) { h = g_qh; l = g_ql; }
    else if (which == 2) { h = g_wh; l = g_wl; }
    else                 { h = g_ph; l = g_pl; }
    for (int i = blockIdx.x * blockDim.x + threadIdx.x; i < n4;
         i += gridDim.x * blockDim.x) {
        float4 v = src[i];
        __nv_bfloat16 h0,l0,h1,l1,h2,l2,h3,l3;
        bsplit(v.x, h0, l0); bsplit(v.y, h1, l1);
        bsplit(v.z, h2, l2); bsplit(v.w, h3, l3);
        uint2 ph; ph.x = bpack(h0, h1); ph.y = bpack(h2, h3);
        uint2 pl; pl.x = bpack(l0, l1); pl.y = bpack(l2, l3);
        *(uint2*)&h[(size_t)i * 4] = ph;
        *(uint2*)&l[(size_t)i * 4] = pl;
    }
}

// ---------------------------------------------------------------------------
// bf16x3 GEMM, cp.async 2-stage pipelined. Block 128(M) x 128(N), BK=16,
// 256 threads, 8 warps (2Mx4N), warp 64x32 = 4 m16-frags x 4 n8-frags.
// Per k16 iter: 12 LDSM.x4, 48 MMA; loads for iter i+1 in flight during
// compute of iter i. Smem: 2 stages x (A hi/lo 128x24 + B hi/lo 16x136).
// ---------------------------------------------------------------------------
#define A_STG (128 * 24)
#define B_STG (16 * 136)

__device__ __forceinline__ void gemm_main(
    const __nv_bfloat16* __restrict__ Agh, const __nv_bfloat16* __restrict__ Agl,
    const __nv_bfloat16* __restrict__ Bgh, const __nv_bfloat16* __restrict__ Bgl,
    int ldb, int m0, int n0,
    __nv_bfloat16* Ash, __nv_bfloat16* Asl,      // [2][128*24]
    __nv_bfloat16* Bsh, __nv_bfloat16* Bsl,      // [2][16*136]
    float (&acc)[4][4][4])
{
    const int tid  = threadIdx.x;
    const int lane = tid & 31;
    const int wid  = tid >> 5;
    const int warpM = wid >> 2;          // 0..1
    const int warpN = wid & 3;           // 0..3

    #pragma unroll
    for (int mt = 0; mt < 4; mt++)
        #pragma unroll
        for (int nf = 0; nf < 4; nf++)
            #pragma unroll
            for (int r = 0; r < 4; r++) acc[mt][nf][r] = 0.f;

    // cp.async indexing: A 128x16 (2 chunks/row), B 16x128 (16 chunks/row)
    const int arow = tid >> 1, acol = (tid & 1) << 3;
    const int brow = tid >> 4, bcol = (tid & 15) << 3;

    const __nv_bfloat16* pAh = Agh + (size_t)(m0 + arow) * 1024 + acol;
    const __nv_bfloat16* pAl = Agl + (size_t)(m0 + arow) * 1024 + acol;
    const __nv_bfloat16* pBh = Bgh + (size_t)brow * ldb + n0 + bcol;
    const __nv_bfloat16* pBl = Bgl + (size_t)brow * ldb + n0 + bcol;

    const uint32_t aDh = s2u(Ash) + (arow * 24 + acol) * 2;
    const uint32_t aDl = s2u(Asl) + (arow * 24 + acol) * 2;
    const uint32_t bDh = s2u(Bsh) + (brow * 136 + bcol) * 2;
    const uint32_t bDl = s2u(Bsl) + (brow * 136 + bcol) * 2;

    // prologue: stage 0 <- k=0
    cpa16(aDh, pAh);
    cpa16(aDl, pAl);
    cpa16(bDh, pBh);
    cpa16(bDl, pBl);
    CP_COMMIT();

    const uint32_t aBase = s2u(Ash);
    const uint32_t alBase = s2u(Asl);
    const uint32_t bBase = s2u(Bsh);
    const uint32_t blBase = s2u(Bsl);

    const int arow_f = lane & 15;
    const int acol_f = (lane >> 4) << 3;
    const int brow_f = (lane & 7) + ((lane >> 3) & 1) * 8;

    for (int it = 0; it < 64; it++) {
        const int buf = it & 1;
        if (it + 1 < 64) {
            const int k1 = (it + 1) * 16;
            const uint32_t so = (buf ^ 1) ? 1u : 0u;
            cpa16(aDh + so * (A_STG * 2), pAh + k1);
            cpa16(aDl + so * (A_STG * 2), pAl + k1);
            cpa16(bDh + so * (B_STG * 2), pBh + (size_t)k1 * ldb);
            cpa16(bDl + so * (B_STG * 2), pBl + (size_t)k1 * ldb);
            CP_COMMIT();
            CP_WAIT1();
        } else {
            CP_WAIT0();
        }
        __syncthreads();

        const uint32_t aOff  = aBase  + buf * (A_STG * 2);
        const uint32_t alOff = alBase + buf * (A_STG * 2);
        const uint32_t bOff  = bBase  + buf * (B_STG * 2);
        const uint32_t blOff = blBase + buf * (B_STG * 2);

        // A fragments (hi + lo)
        uint32_t ah[4][4], al[4][4];
        #pragma unroll
        for (int mt = 0; mt < 4; mt++) {
            const int row = warpM * 64 + mt * 16 + arow_f;
            LDSM_X4(ah[mt][0], ah[mt][1], ah[mt][2], ah[mt][3],
                    aOff + (row * 24 + acol_f) * 2);
            LDSM_X4(al[mt][0], al[mt][1], al[mt][2], al[mt][3],
                    alOff + (row * 24 + acol_f) * 2);
        }
        // B fragments (hi + lo), trans from [k][n]
        uint32_t bh[4][2], bl[4][2];
        #pragma unroll
        for (int pp = 0; pp < 2; pp++) {
            const int col = warpN * 32 + pp * 16 + acol_f;
            LDSM_X4T(bh[2*pp][0], bh[2*pp][1], bh[2*pp+1][0], bh[2*pp+1][1],
                     bOff + (brow_f * 136 + col) * 2);
            LDSM_X4T(bl[2*pp][0], bl[2*pp][1], bl[2*pp+1][0], bl[2*pp+1][1],
                     blOff + (brow_f * 136 + col) * 2);
        }
        #pragma unroll
        for (int mt = 0; mt < 4; mt++)
            #pragma unroll
            for (int nf = 0; nf < 4; nf++) {
                mma_bf16(acc[mt][nf], ah[mt], bh[nf][0], bh[nf][1]);
                mma_bf16(acc[mt][nf], ah[mt], bl[nf][0], bl[nf][1]);
                mma_bf16(acc[mt][nf], al[mt], bh[nf][0], bh[nf][1]);
            }
        __syncthreads();     // compute(buf) done before buf reload at it+2
    }
}

// ---------------------------------------------------------------------------
// QKV projection: [8192,3072] = A @ W + b; scattered to q/k/v bf16 hi/lo
// planes in [B,H,S,HD] layout. q region pre-scaled by 1/sqrt(HD).
// ---------------------------------------------------------------------------
__global__ __launch_bounds__(256) void qkv_gemm(const float* __restrict__ bias)
{
    __shared__ __align__(16) __nv_bfloat16 Ash[2 * A_STG], Asl[2 * A_STG];
    __shared__ __align__(16) __nv_bfloat16 Bsh[2 * B_STG], Bsl[2 * B_STG];

    const int n0 = blockIdx.x * 128;
    const int m0 = blockIdx.y * 128;
    const int region = n0 >> 10;              // 0=q, 1=k, 2=v

    const __nv_bfloat16* Agh = (region == 0) ? g_qh : g_xh;
    const __nv_bfloat16* Agl = (region == 0) ? g_ql : g_xl;
    __nv_bfloat16* dh = (region == 0) ? gQh : ((region == 1) ? gKh : gVh);
    __nv_bfloat16* dl = (region == 0) ? gQl : ((region == 1) ? gKl : gVl);
    const float scale = (region == 0) ? 0.125f : 1.0f;

    float acc[4][4][4];
    gemm_main(Agh, Agl, g_wh, g_wl, 3072, m0, n0, Ash, Asl, Bsh, Bsl, acc);

    const int lane = threadIdx.x & 31;
    const int wid  = threadIdx.x >> 5;
    const int warpM = wid >> 2, warpN = wid & 3;
    const int g = lane >> 2, tg = lane & 3;

    #pragma unroll
    for (int mt = 0; mt < 4; mt++) {
        #pragma unroll
        for (int nf = 0; nf < 4; nf++) {
            const int col = n0 + warpN * 32 + nf * 8 + 2 * tg;
            const int nn = col & 1023;
            const int hh = nn >> 6, dd = nn & 63;
            const float b0v = bias[col], b1v = bias[col + 1];
            #pragma unroll
            for (int half = 0; half < 2; half++) {
                const int row = m0 + warpM * 64 + mt * 16 + g + 8 * half;
                const int bb = row >> 10, ss = row & 1023;
                float v0 = (acc[mt][nf][2*half + 0] + b0v) * scale;
                float v1 = (acc[mt][nf][2*half + 1] + b1v) * scale;
                __nv_bfloat16 h0, l0, h1, l1;
                bsplit(v0, h0, l0); bsplit(v1, h1, l1);
                const size_t o = ((size_t)((bb * NH + hh) * NS + ss)) * DH + dd;
                *(uint32_t*)&dh[o] = bpack(h0, h1);
                *(uint32_t*)&dl[o] = bpack(l0, l1);
            }
        }
    }
}

// ---------------------------------------------------------------------------
// Output projection: out[8192,1024] = attn_out @ Wp + bp (fp32 out)
// ---------------------------------------------------------------------------
__global__ __launch_bounds__(256) void proj_gemm(const float* __restrict__ bias,
                                                 float* __restrict__ out)
{
    __shared__ __align__(16) __nv_bfloat16 Ash[2 * A_STG], Asl[2 * A_STG];
    __shared__ __align__(16) __nv_bfloat16 Bsh[2 * B_STG], Bsl[2 * B_STG];

    const int n0 = blockIdx.x * 128;
    const int m0 = blockIdx.y * 128;

    float acc[4][4][4];
    gemm_main(gAh, gAl, g_ph, g_pl, 1024, m0, n0, Ash, Asl, Bsh, Bsl, acc);

    const int lane = threadIdx.x & 31;
    const int wid  = threadIdx.x >> 5;
    const int warpM = wid >> 2, warpN = wid & 3;
    const int g = lane >> 2, tg = lane & 3;

    #pragma unroll
    for (int mt = 0; mt < 4; mt++) {
        #pragma unroll
        for (int nf = 0; nf < 4; nf++) {
            const int col = n0 + warpN * 32 + nf * 8 + 2 * tg;
            const float b0v = bias[col], b1v = bias[col + 1];
            #pragma unroll
            for (int half = 0; half < 2; half++) {
                const int row = m0 + warpM * 64 + mt * 16 + g + 8 * half;
                float2 st;
                st.x = acc[mt][nf][2*half + 0] + b0v;
                st.y = acc[mt][nf][2*half + 1] + b1v;
                *(float2*)&out[(size_t)row * NXD + col] = st;
            }
        }
    }
}

// ---------------------------------------------------------------------------
// Flash attention, bf16x3 tensor-core. Block = 128 q-rows of one (b,h),
// 8 warps, warp = 16-row strip. Q frags register-resident; K/V hi/lo tiles
// in smem. P re-packed from S C-frags into A-frags with bf16 hi/lo split.
// Output written as bf16 hi/lo planes for the projection GEMM.
// (Unchanged from Round 5 passing version.)
// ---------------------------------------------------------------------------
__global__ __launch_bounds__(256) void attn_kernel()
{
    const int qb2 = blockIdx.x;          // 0..7  (128-row q block)
    const int bh  = blockIdx.y;          // 0..127
    const int bb = bh >> 4, hh = bh & 15;
    const size_t off = (size_t)bh * NS * DH;

    __shared__ __align__(16) __nv_bfloat16 SM[4 * 64 * 72];
    __nv_bfloat16* Ksh = SM;             // [64][72]
    __nv_bfloat16* Ksl = SM + 4608;
    __nv_bfloat16* Vsh = SM + 9216;
    __nv_bfloat16* Vsl = SM + 13824;

    const int tid  = threadIdx.x;
    const int lane = tid & 31;
    const int w    = tid >> 5;           // 0..7
    const int g = lane >> 2, tg = lane & 3;
    const int r0 = qb2 * 128 + w * 16;   // warp strip global row base

    // ---- load Q fragments into registers (hi then lo, staged via smem) ----
    uint32_t qfh[4][4], qfl[4][4];
    {
        const __nv_bfloat16* srcs[2] = { gQh + off + (size_t)(qb2 * 128) * DH,
                                         gQl + off + (size_t)(qb2 * 128) * DH };
        #pragma unroll
        for (int ph = 0; ph < 2; ph++) {
            const __nv_bfloat16* src = srcs[ph];
            for (int i = tid; i < 1024; i += 256) {
                const int r = i >> 3, c = (i & 7) << 3;
                *(uint4*)&SM[r * 72 + c] = *(const uint4*)&src[(size_t)r * 64 + c];
            }
            __syncthreads();
            const int qrow = w * 16 + (lane & 15);
            #pragma unroll
            for (int ks = 0; ks < 4; ks++) {
                uint32_t ad = s2u(&SM[qrow * 72 + ks * 16 + ((lane >> 4) << 3)]);
                if (ph == 0) { LDSM_X4(qfh[ks][0], qfh[ks][1], qfh[ks][2], qfh[ks][3], ad); }
                else         { LDSM_X4(qfl[ks][0], qfl[ks][1], qfl[ks][2], qfl[ks][3], ad); }
            }
            __syncthreads();
        }
    }

    float O[8][4];
    #pragma unroll
    for (int nf = 0; nf < 8; nf++)
        #pragma unroll
        for (int r = 0; r < 4; r++) O[nf][r] = 0.f;
    float m0_ = -1e30f, m1_ = -1e30f, l0_ = 0.f, l1_ = 0.f;

    const __nv_bfloat16* Kh_g = gKh + off;
    const __nv_bfloat16* Kl_g = gKl + off;
    const __nv_bfloat16* Vh_g = gVh + off;
    const __nv_bfloat16* Vl_g = gVl + off;

    const int kbmax = 2 * qb2 + 2;
    for (int kb = 0; kb < kbmax; kb++) {
        __syncthreads();
        const size_t tile = (size_t)kb * 64 * DH;
        for (int i = tid; i < 512; i += 256) {
            const int r = i >> 3, c = (i & 7) << 3;
            const size_t gi = tile + (size_t)r * 64 + c;
            *(uint4*)&Ksh[r * 72 + c] = *(const uint4*)&Kh_g[gi];
            *(uint4*)&Ksl[r * 72 + c] = *(const uint4*)&Kl_g[gi];
            *(uint4*)&Vsh[r * 72 + c] = *(const uint4*)&Vh_g[gi];
            *(uint4*)&Vsl[r * 72 + c] = *(const uint4*)&Vl_g[gi];
        }
        __syncthreads();

        if (kb * 64 > r0 + 15) continue;     // fully masked for this warp

        // ---- S = Q K^T ----
        float S[8][4];
        #pragma unroll
        for (int nf = 0; nf < 8; nf++)
            #pragma unroll
            for (int r = 0; r < 4; r++) S[nf][r] = 0.f;

        #pragma unroll
        for (int ks = 0; ks < 4; ks++) {
            uint32_t bhf[8][2], blf[8][2];
            const int nrow = (lane & 7) + ((lane >> 4) << 3);
            const int kcol = ks * 16 + ((lane >> 3) & 1) * 8;
            #pragma unroll
            for (int pp = 0; pp < 4; pp++) {
                uint32_t ad = s2u(&Ksh[(pp * 16 + nrow) * 72 + kcol]);
                LDSM_X4(bhf[2*pp][0], bhf[2*pp][1], bhf[2*pp+1][0], bhf[2*pp+1][1], ad);
                uint32_t ad2 = s2u(&Ksl[(pp * 16 + nrow) * 72 + kcol]);
                LDSM_X4(blf[2*pp][0], blf[2*pp][1], blf[2*pp+1][0], blf[2*pp+1][1], ad2);
            }
            #pragma unroll
            for (int nf = 0; nf < 8; nf++) {
                mma_bf16(S[nf], qfh[ks], bhf[nf][0], bhf[nf][1]);
                mma_bf16(S[nf], qfh[ks], blf[nf][0], blf[nf][1]);
                mma_bf16(S[nf], qfl[ks], bhf[nf][0], bhf[nf][1]);
            }
        }

        // ---- causal mask (diagonal-overlap tiles only) ----
        if (kb * 64 + 63 > r0) {
            #pragma unroll
            for (int nf = 0; nf < 8; nf++) {
                #pragma unroll
                for (int e = 0; e < 4; e++) {
                    const int j = kb * 64 + nf * 8 + 2 * tg + (e & 1);
                    const int rr = r0 + g + ((e >= 2) ? 8 : 0);
                    if (j > rr) S[nf][e] = -1e30f;
                }
            }
        }

        // ---- online softmax (rows g and g+8; quad-reduce over tg) ----
        float mx0 = -1e30f, mx1 = -1e30f;
        #pragma unroll
        for (int nf = 0; nf < 8; nf++) {
            mx0 = fmaxf(mx0, fmaxf(S[nf][0], S[nf][1]));
            mx1 = fmaxf(mx1, fmaxf(S[nf][2], S[nf][3]));
        }
        mx0 = fmaxf(mx0, __shfl_xor_sync(0xffffffffu, mx0, 1));
        mx0 = fmaxf(mx0, __shfl_xor_sync(0xffffffffu, mx0, 2));
        mx1 = fmaxf(mx1, __shfl_xor_sync(0xffffffffu, mx1, 1));
        mx1 = fmaxf(mx1, __shfl_xor_sync(0xffffffffu, mx1, 2));
        const float mn0 = fmaxf(m0_, mx0), mn1 = fmaxf(m1_, mx1);
        const float sc0 = __expf(m0_ - mn0), sc1 = __expf(m1_ - mn1);
        float rs0 = 0.f, rs1 = 0.f;
        #pragma unroll
        for (int nf = 0; nf < 8; nf++) {
            S[nf][0] = __expf(S[nf][0] - mn0);
            S[nf][1] = __expf(S[nf][1] - mn0);
            S[nf][2] = __expf(S[nf][2] - mn1);
            S[nf][3] = __expf(S[nf][3] - mn1);
            rs0 += S[nf][0] + S[nf][1];
            rs1 += S[nf][2] + S[nf][3];
        }
        rs0 += __shfl_xor_sync(0xffffffffu, rs0, 1);
        rs0 += __shfl_xor_sync(0xffffffffu, rs0, 2);
        rs1 += __shfl_xor_sync(0xffffffffu, rs1, 1);
        rs1 += __shfl_xor_sync(0xffffffffu, rs1, 2);
        l0_ = l0_ * sc0 + rs0;  l1_ = l1_ * sc1 + rs1;
        m0_ = mn0;  m1_ = mn1;
        #pragma unroll
        for (int nf = 0; nf < 8; nf++) {
            O[nf][0] *= sc0; O[nf][1] *= sc0;
            O[nf][2] *= sc1; O[nf][3] *= sc1;
        }

        // ---- O += P V ----
        #pragma unroll
        for (int ks = 0; ks < 4; ks++) {
            // pack P A-fragments (hi/lo) from S frags 2ks, 2ks+1
            uint32_t pah[4], pal[4];
            {
                __nv_bfloat16 h0,l0,h1,l1;
                bsplit(S[2*ks][0], h0, l0); bsplit(S[2*ks][1], h1, l1);
                pah[0] = bpack(h0, h1); pal[0] = bpack(l0, l1);
                bsplit(S[2*ks][2], h0, l0); bsplit(S[2*ks][3], h1, l1);
                pah[1] = bpack(h0, h1); pal[1] = bpack(l0, l1);
                bsplit(S[2*ks+1][0], h0, l0); bsplit(S[2*ks+1][1], h1, l1);
                pah[2] = bpack(h0, h1); pal[2] = bpack(l0, l1);
                bsplit(S[2*ks+1][2], h0, l0); bsplit(S[2*ks+1][3], h1, l1);
                pah[3] = bpack(h0, h1); pal[3] = bpack(l0, l1);
            }
            uint32_t vhf[8][2], vlf[8][2];
            const int krow = ks * 16 + (lane & 7) + ((lane >> 3) & 1) * 8;
            const int ncol = ((lane >> 4) << 3);
            #pragma unroll
            for (int pp = 0; pp < 4; pp++) {
                uint32_t ad = s2u(&Vsh[krow * 72 + pp * 16 + ncol]);
                LDSM_X4T(vhf[2*pp][0], vhf[2*pp][1], vhf[2*pp+1][0], vhf[2*pp+1][1], ad);
                uint32_t ad2 = s2u(&Vsl[krow * 72 + pp * 16 + ncol]);
                LDSM_X4T(vlf[2*pp][0], vlf[2*pp][1], vlf[2*pp+1][0], vlf[2*pp+1][1], ad2);
            }
            #pragma unroll
            for (int nf = 0; nf < 8; nf++) {
                mma_bf16(O[nf], pah, vhf[nf][0], vhf[nf][1]);
                mma_bf16(O[nf], pah, vlf[nf][0], vlf[nf][1]);
                mma_bf16(O[nf], pal, vhf[nf][0], vhf[nf][1]);
            }
        }
    }

    // ---- epilogue: O/l -> bf16 hi/lo planes of attn output [B,S,NX] ----
    const float inv0 = 1.f / l0_, inv1 = 1.f / l1_;
    const int row0 = r0 + g, row1 = r0 + g + 8;
    const size_t base0 = ((size_t)bb * NS + row0) * NXD + hh * 64;
    const size_t base1 = ((size_t)bb * NS + row1) * NXD + hh * 64;
    #pragma unroll
    for (int nf = 0; nf < 8; nf++) {
        const int d = nf * 8 + 2 * tg;
        __nv_bfloat16 h0,l0,h1,l1;
        bsplit(O[nf][0] * inv0, h0, l0); bsplit(O[nf][1] * inv0, h1, l1);
        *(uint32_t*)&gAh[base0 + d] = bpack(h0, h1);
        *(uint32_t*)&gAl[base0 + d] = bpack(l0, l1);
        bsplit(O[nf][2] * inv1, h0, l0); bsplit(O[nf][3] * inv1, h1, l1);
        *(uint32_t*)&gAh[base1 + d] = bpack(h0, h1);
        *(uint32_t*)&gAl[base1 + d] = bpack(l0, l1);
    }
}

// ---------------------------------------------------------------------------
extern "C" void kernel_launch(void* const* d_in, const int* in_sizes, int n_in,
                              void* d_out, int out_size)
{
    (void)in_sizes; (void)n_in; (void)out_size;
    const float* x        = (const float*)d_in[0];
    const float* query    = (const float*)d_in[1];
    const float* c_attn_w = (const float*)d_in[2];
    const float* c_attn_b = (const float*)d_in[3];
    const float* c_proj_w = (const float*)d_in[4];
    const float* c_proj_b = (const float*)d_in[5];
    float* out = (float*)d_out;

    split_kernel<<<2048, 256>>>((const float4*)x,        0, NB*NS*NXD/4);
    split_kernel<<<2048, 256>>>((const float4*)query,    1, NB*NS*NXD/4);
    split_kernel<<<2048, 256>>>((const float4*)c_attn_w, 2, NXD*3*NXD/4);
    split_kernel<<<1024, 256>>>((const float4*)c_proj_w, 3, NXD*NXD/4);

    qkv_gemm<<<dim3(24, 64), 256>>>(c_attn_b);
    attn_kernel<<<dim3(8, 128), 256>>>();
    proj_gemm<<<dim3(8, 64), 256>>>(c_proj_b, out);
}